// round 11
// baseline (speedup 1.0000x reference)
#include <cuda_runtime.h>
#include <cstdint>

#define NB 8
#define NN 256
#define ND 128
#define NH 256
#define NK 128

typedef unsigned long long u64t;

// ---------------- scratch ----------------------------------------------------
__device__ float g_hi[NB*NN*NH];      // hi + b1 folded in   (2 MB)
__device__ float g_hj[NB*NN*NH];      // hj                  (2 MB)

// ---------------- packed f32x2 helpers ---------------------------------------
__device__ __forceinline__ u64t add2(u64t a, u64t b) {
    u64t r; asm("add.rn.f32x2 %0, %1, %2;" : "=l"(r) : "l"(a), "l"(b)); return r;
}
__device__ __forceinline__ u64t fma2(u64t a, u64t b, u64t c) {
    u64t r; asm("fma.rn.f32x2 %0, %1, %2, %3;" : "=l"(r) : "l"(a), "l"(b), "l"(c)); return r;
}
__device__ __forceinline__ u64t relu2(u64t a) {
    float lo, hi;
    asm("mov.b64 {%0,%1}, %2;" : "=f"(lo), "=f"(hi) : "l"(a));
    lo = fmaxf(lo, 0.f); hi = fmaxf(hi, 0.f);
    u64t r; asm("mov.b64 %0, {%1,%2};" : "=l"(r) : "f"(lo), "f"(hi)); return r;
}
__device__ __forceinline__ float hsum2(u64t a) {
    float lo, hi;
    asm("mov.b64 {%0,%1}, %2;" : "=f"(lo), "=f"(hi) : "l"(a));
    return lo + hi;
}
__device__ __forceinline__ float ex2a(float v) {
    float y;
    asm("ex2.approx.f32 %0, %1;" : "=f"(y) : "f"(v));
    return y;
}

// ---------------- Kernel A: [2048x128] @ [128x512] with smem-staged W1 -------
__global__ __launch_bounds__(128) void k_embed(const float* __restrict__ ae,
                                               const float* __restrict__ W1,
                                               const float* __restrict__ b1) {
    __shared__ float sa[32][129];
    __shared__ float wseg[64][64];

    int row0  = blockIdx.x * 32;
    int hcol0 = blockIdx.y * 64;
    bool isb  = hcol0 >= 256;
    int gcol  = hcol0 & 255;
    int tid   = threadIdx.x;
    int hq    = tid & 15;
    int rg    = tid >> 4;

    #pragma unroll
    for (int s = 0; s < 8; s++) {
        int idx = s*128 + tid;
        int r = idx >> 5, q = idx & 31;
        float4 v = *(const float4*)&ae[(size_t)(row0 + r)*ND + q*4];
        sa[r][q*4+0] = v.x; sa[r][q*4+1] = v.y;
        sa[r][q*4+2] = v.z; sa[r][q*4+3] = v.w;
    }

    float4 bb = isb ? make_float4(0.f,0.f,0.f,0.f)
                    : *(const float4*)&b1[gcol + hq*4];
    float4 acc0 = bb, acc1 = bb, acc2 = bb, acc3 = bb;

    const float* wbase = W1 + (size_t)(isb ? 128 : 0)*NH + gcol;

    #pragma unroll
    for (int kc = 0; kc < 128; kc += 64) {
        __syncthreads();
        #pragma unroll
        for (int s = 0; s < 8; s++) {
            int idx = s*128 + tid;
            int kk = idx >> 4, q = idx & 15;
            *(float4*)&wseg[kk][q*4] =
                *(const float4*)&wbase[(size_t)(kc + kk)*NH + q*4];
        }
        __syncthreads();

        #pragma unroll 4
        for (int kk = 0; kk < 64; kk++) {
            float4 w = *(const float4*)&wseg[kk][hq*4];
            float a0 = sa[rg*4+0][kc+kk];
            float a1 = sa[rg*4+1][kc+kk];
            float a2 = sa[rg*4+2][kc+kk];
            float a3 = sa[rg*4+3][kc+kk];
            acc0.x = fmaf(a0,w.x,acc0.x); acc0.y = fmaf(a0,w.y,acc0.y);
            acc0.z = fmaf(a0,w.z,acc0.z); acc0.w = fmaf(a0,w.w,acc0.w);
            acc1.x = fmaf(a1,w.x,acc1.x); acc1.y = fmaf(a1,w.y,acc1.y);
            acc1.z = fmaf(a1,w.z,acc1.z); acc1.w = fmaf(a1,w.w,acc1.w);
            acc2.x = fmaf(a2,w.x,acc2.x); acc2.y = fmaf(a2,w.y,acc2.y);
            acc2.z = fmaf(a2,w.z,acc2.z); acc2.w = fmaf(a2,w.w,acc2.w);
            acc3.x = fmaf(a3,w.x,acc3.x); acc3.y = fmaf(a3,w.y,acc3.y);
            acc3.z = fmaf(a3,w.z,acc3.z); acc3.w = fmaf(a3,w.w,acc3.w);
        }
    }

    float* dst = isb ? g_hj : g_hi;
    int c = (isb ? hcol0 - 256 : hcol0) + hq*4;
    int r0 = row0 + rg*4;
    *(float4*)&dst[(size_t)(r0+0)*NH + c] = acc0;
    *(float4*)&dst[(size_t)(r0+1)*NH + c] = acc1;
    *(float4*)&dst[(size_t)(r0+2)*NH + c] = acc2;
    *(float4*)&dst[(size_t)(r0+3)*NH + c] = acc3;
}

// ---------------- Kernel B: R5 structure + TMA bulk stores --------------------
// 32(i) x 16(j) tile, 128 threads, 2x2 pairs/thread. Phase 2 computes each
// half-row (8 j x 128 k = 4KB contiguous) into a per-warp smem buffer and
// issues ONE cp.async.bulk store instead of 512 STG.128s.
#define TI 32
#define TJ 16
#define HCH 128
#define PADW 132

// dynamic smem layout (floats):
// region A: phase1 shi(32*132=4224)+shj(16*132=2112)=6336; phase2: 4x1024 staging
#define OFF_SHI   0
#define OFF_SHJ   (TI*PADW)                // 4224
#define OFF_SW0   6336
#define OFF_SW1   (OFF_SW0 + NH)           // 6592
#define OFF_SX    (OFF_SW1 + NH)           // 6848
#define OFF_SMUL  (OFF_SX + TI*TJ)         // 7360
#define OFF_SBIAS (OFF_SMUL + TI*TJ)       // 7872
#define SMEM_FLOATS (OFF_SBIAS + TI*TJ)    // 8384
#define SMEM_BYTES  (SMEM_FLOATS*4)        // 33536

#define PSTEP4(A0,A1,C0,C1,W0,W1v) {                                     \
    u64t r00 = relu2(add2((A0), (C0)));                                   \
    u64t r01 = relu2(add2((A0), (C1)));                                   \
    u64t r10 = relu2(add2((A1), (C0)));                                   \
    u64t r11 = relu2(add2((A1), (C1)));                                   \
    acc00a = fma2(r00, (W0), acc00a); acc00b = fma2(r00, (W1v), acc00b);  \
    acc01a = fma2(r01, (W0), acc01a); acc01b = fma2(r01, (W1v), acc01b);  \
    acc10a = fma2(r10, (W0), acc10a); acc10b = fma2(r10, (W1v), acc10b);  \
    acc11a = fma2(r11, (W0), acc11a); acc11b = fma2(r11, (W1v), acc11b); }

__global__ __launch_bounds__(128, 6) void k_fused(
        const float* __restrict__ x,
        const float* __restrict__ W2,
        const float* __restrict__ b2,
        const float* __restrict__ means,
        const float* __restrict__ temps,
        float* __restrict__ out) {
    extern __shared__ float sm[];
    float* shi  = sm + OFF_SHI;
    float* shj  = sm + OFF_SHJ;
    float* sw0  = sm + OFF_SW0;
    float* sw1  = sm + OFF_SW1;
    float* sx   = sm + OFF_SX;
    float* smul = sm + OFF_SMUL;
    float* sbias= sm + OFF_SBIAS;

    int b  = blockIdx.z;
    int i0 = blockIdx.y * TI;
    int j0 = blockIdx.x * TJ;
    int tid  = threadIdx.x;                // 0..127
    int lane = tid & 31;
    int wid  = tid >> 5;                   // 0..3

    // one-time loads: W2 columns and x tile
    #pragma unroll
    for (int h = tid; h < NH; h += 128) {
        sw0[h] = W2[2*h];
        sw1[h] = W2[2*h + 1];
    }
    {
        int r = tid >> 2;
        int c = tid & 3;
        *(float4*)&sx[r*TJ + c*4] =
            *(const float4*)&x[(size_t)(b*NN + i0 + r)*NN + j0 + c*4];
    }

    const float* hi_base = g_hi + (size_t)(b*NN + i0)*NH;
    const float* hj_base = g_hj + (size_t)(b*NN + j0)*NH;

    int tjj = tid & 7;                     // j rows tjj, tjj+8
    int tii = tid >> 3;                    // i rows tii, tii+16

    u64t acc00a=0ull, acc00b=0ull, acc01a=0ull, acc01b=0ull;
    u64t acc10a=0ull, acc10b=0ull, acc11a=0ull, acc11b=0ull;

    #pragma unroll
    for (int p = 0; p < 2; p++) {
        __syncthreads();
        // stage h-chunk: shi 32x128, shj 16x128 (1536 float4 total)
        #pragma unroll
        for (int s5 = 0; s5 < 12; s5++) {
            int idx = s5*128 + tid;
            if (idx < 1024) {
                int r = idx >> 5, c = idx & 31;
                *(float4*)&shi[r*PADW + c*4] =
                    *(const float4*)&hi_base[(size_t)r*NH + p*HCH + c*4];
            } else {
                int id2 = idx - 1024;
                int r = id2 >> 5, c = id2 & 31;
                *(float4*)&shj[r*PADW + c*4] =
                    *(const float4*)&hj_base[(size_t)r*NH + p*HCH + c*4];
            }
        }
        __syncthreads();

        const float* wp0 = sw0 + p*HCH;
        const float* wp1 = sw1 + p*HCH;
        #pragma unroll 2
        for (int h4 = 0; h4 < HCH/4; h4++) {
            ulonglong2 A0 = *(const ulonglong2*)&shi[(tii   )*PADW + h4*4];
            ulonglong2 A1 = *(const ulonglong2*)&shi[(tii+16)*PADW + h4*4];
            ulonglong2 C0 = *(const ulonglong2*)&shj[(tjj   )*PADW + h4*4];
            ulonglong2 C1 = *(const ulonglong2*)&shj[(tjj+ 8)*PADW + h4*4];
            ulonglong2 W0 = *(const ulonglong2*)&wp0[h4*4];
            ulonglong2 W1v= *(const ulonglong2*)&wp1[h4*4];
            PSTEP4(A0.x, A1.x, C0.x, C1.x, W0.x, W1v.x);
            PSTEP4(A0.y, A1.y, C0.y, C1.y, W0.y, W1v.y);
        }
    }

    // mul/bias to their own smem arrays
    {
        const float s = 0.0625f;           // 1/sqrt(2*128)
        float cb0 = __ldg(&b2[0]) * s;
        float cb1 = __ldg(&b2[1]) * s;
        smul [(tii   )*TJ + tjj  ] = fmaf(hsum2(acc00a), s, cb0);
        sbias[(tii   )*TJ + tjj  ] = fmaf(hsum2(acc00b), s, cb1);
        smul [(tii   )*TJ + tjj+8] = fmaf(hsum2(acc01a), s, cb0);
        sbias[(tii   )*TJ + tjj+8] = fmaf(hsum2(acc01b), s, cb1);
        smul [(tii+16)*TJ + tjj  ] = fmaf(hsum2(acc10a), s, cb0);
        sbias[(tii+16)*TJ + tjj  ] = fmaf(hsum2(acc10b), s, cb1);
        smul [(tii+16)*TJ + tjj+8] = fmaf(hsum2(acc11a), s, cb0);
        sbias[(tii+16)*TJ + tjj+8] = fmaf(hsum2(acc11b), s, cb1);
    }
    __syncthreads();                       // mul/bias visible; shi now dead

    // ---------- phase 2: RBF into per-warp smem buffer + TMA bulk stores ----
    const float L2E = 1.4426950408889634f;
    int k0 = lane * 4;
    float4 mm4 = *(const float4*)&means[k0];
    float4 tt4 = *(const float4*)&temps[k0];
    float nA0 = -fabsf(tt4.x)*L2E, nA1 = -fabsf(tt4.y)*L2E;
    float nA2 = -fabsf(tt4.z)*L2E, nA3 = -fabsf(tt4.w)*L2E;
    float pB0 = -2.f*nA0*mm4.x, pB1 = -2.f*nA1*mm4.y;
    float pB2 = -2.f*nA2*mm4.z, pB3 = -2.f*nA3*mm4.w;
    float qC0 = nA0*mm4.x*mm4.x, qC1 = nA1*mm4.y*mm4.y;
    float qC2 = nA2*mm4.z*mm4.z, qC3 = nA3*mm4.w*mm4.w;

    float* buf = sm + wid*1024;            // 4KB staging per warp (aliases shi)
    unsigned int buf_u32 =
        (unsigned int)__cvta_generic_to_shared(buf);

    #pragma unroll 1
    for (int r = 0; r < 8; r++) {
        int i_loc = wid*8 + r;
        float* gdst_row = out + ((size_t)(b*NN + i0 + i_loc)*NN + j0)*NK;
        #pragma unroll
        for (int hb = 0; hb < 2; hb++) {
            // buffer must be free (prior bulk's smem read done)
            if (lane == 0)
                asm volatile("cp.async.bulk.wait_group.read 0;" ::: "memory");
            __syncwarp();

            #pragma unroll
            for (int g = 0; g < 2; g++) {
                int pb = i_loc*TJ + hb*8 + g*4;
                float4 m4 = *(const float4*)&smul[pb];
                float4 b4 = *(const float4*)&sbias[pb];
                float4 xv = *(const float4*)&sx[pb];
                #define RBF_STS(M,X,BV,SLOT) {                                \
                    float v = fmaf((M), (X), (BV));                            \
                    float e0 = ex2a(fmaf(fmaf(nA0, v, pB0), v, qC0));          \
                    float e1 = ex2a(fmaf(fmaf(nA1, v, pB1), v, qC1));          \
                    float e2 = ex2a(fmaf(fmaf(nA2, v, pB2), v, qC2));          \
                    float e3 = ex2a(fmaf(fmaf(nA3, v, pB3), v, qC3));          \
                    *(float4*)&buf[(SLOT)*NK + k0] =                           \
                        make_float4(e0, e1, e2, e3); }
                RBF_STS(m4.x, xv.x, b4.x, g*4+0);
                RBF_STS(m4.y, xv.y, b4.y, g*4+1);
                RBF_STS(m4.z, xv.z, b4.z, g*4+2);
                RBF_STS(m4.w, xv.w, b4.w, g*4+3);
                #undef RBF_STS
            }

            asm volatile("fence.proxy.async.shared::cta;" ::: "memory");
            __syncwarp();
            if (lane == 0) {
                asm volatile(
                    "cp.async.bulk.global.shared::cta.bulk_group [%0], [%1], %2;"
                    :: "l"(gdst_row + hb*8*NK), "r"(buf_u32), "r"(4096)
                    : "memory");
                asm volatile("cp.async.bulk.commit_group;" ::: "memory");
            }
        }
    }
    // ensure all bulk stores complete before exit
    if (lane == 0)
        asm volatile("cp.async.bulk.wait_group 0;" ::: "memory");
}

// ---------------- launch ------------------------------------------------------
extern "C" void kernel_launch(void* const* d_in, const int* in_sizes, int n_in,
                              void* d_out, int out_size) {
    const float* x     = (const float*)d_in[0];   // (B,N,N)
    const float* ae    = (const float*)d_in[1];   // (B,N,D)
    const float* W1    = (const float*)d_in[2];   // (2D,H)
    const float* b1    = (const float*)d_in[3];   // (H)
    const float* W2    = (const float*)d_in[4];   // (H,2)
    const float* b2    = (const float*)d_in[5];   // (2)
    const float* means = (const float*)d_in[6];   // (K)
    const float* temps = (const float*)d_in[7];   // (K)
    float* out = (float*)d_out;                   // (B,N,N,K)

    dim3 gA(NB*NN/32, 8);                         // 512 blocks
    k_embed<<<gA, 128>>>(ae, W1, b1);

    cudaFuncSetAttribute(k_fused, cudaFuncAttributeMaxDynamicSharedMemorySize,
                         SMEM_BYTES);
    dim3 gB(NN/TJ, NN/TI, NB);                    // (16, 8, 8) = 1024 blocks
    k_fused<<<gB, 128, SMEM_BYTES>>>(x, W2, b2, means, temps, out);
}

// round 12
// speedup vs baseline: 1.0663x; 1.0663x over previous
#include <cuda_runtime.h>

#define NB 8
#define NN 256
#define ND 128
#define NH 256
#define NK 128

typedef unsigned long long u64t;

// ---------------- scratch ----------------------------------------------------
__device__ float g_hi[NB*NN*NH];      // hi + b1 folded in   (2 MB)
__device__ float g_hj[NB*NN*NH];      // hj                  (2 MB)

// ---------------- packed f32x2 helpers ---------------------------------------
__device__ __forceinline__ u64t add2(u64t a, u64t b) {
    u64t r; asm("add.rn.f32x2 %0, %1, %2;" : "=l"(r) : "l"(a), "l"(b)); return r;
}
__device__ __forceinline__ u64t fma2(u64t a, u64t b, u64t c) {
    u64t r; asm("fma.rn.f32x2 %0, %1, %2, %3;" : "=l"(r) : "l"(a), "l"(b), "l"(c)); return r;
}
__device__ __forceinline__ u64t relu2(u64t a) {
    float lo, hi;
    asm("mov.b64 {%0,%1}, %2;" : "=f"(lo), "=f"(hi) : "l"(a));
    lo = fmaxf(lo, 0.f); hi = fmaxf(hi, 0.f);
    u64t r; asm("mov.b64 %0, {%1,%2};" : "=l"(r) : "f"(lo), "f"(hi)); return r;
}
__device__ __forceinline__ float hsum2(u64t a) {
    float lo, hi;
    asm("mov.b64 {%0,%1}, %2;" : "=f"(lo), "=f"(hi) : "l"(a));
    return lo + hi;
}
__device__ __forceinline__ float ex2a(float v) {
    float y;
    asm("ex2.approx.f32 %0, %1;" : "=f"(y) : "f"(v));
    return y;
}

// ---------------- Kernel A: [2048x128] @ [128x512], vectorized LDS -----------
// Block = 32 rows x 64 cols, 128 threads: thread owns 4 rows x 1 col-quad.
// Inner loop reads BOTH sa and wseg as float4: 8 LDS.128 per 64 FMA per k4
// (was 4 LDS.128 + 16 scalar LDS). sa padded to 132 for 16B alignment.
__global__ __launch_bounds__(128) void k_embed(const float* __restrict__ ae,
                                               const float* __restrict__ W1,
                                               const float* __restrict__ b1) {
    __shared__ float sa[32][132];          // 16.9 KB (132: f4-aligned, 4-bank skew)
    __shared__ float wseg[64][64];         // 16 KB

    int row0  = blockIdx.x * 32;
    int hcol0 = blockIdx.y * 64;           // flat col 0..511
    bool isb  = hcol0 >= 256;
    int gcol  = hcol0 & 255;
    int tid   = threadIdx.x;
    int hq    = tid & 15;                  // col quad 0..15
    int rg    = tid >> 4;                  // 0..7 -> rows rg*4..rg*4+3

    // stage A tile 32x128 (float4 both sides)
    #pragma unroll
    for (int s = 0; s < 8; s++) {
        int idx = s*128 + tid;             // 1024 float4
        int r = idx >> 5, q = idx & 31;
        *(float4*)&sa[r][q*4] = *(const float4*)&ae[(size_t)(row0 + r)*ND + q*4];
    }

    float4 bb = isb ? make_float4(0.f,0.f,0.f,0.f)
                    : *(const float4*)&b1[gcol + hq*4];
    float4 acc0 = bb, acc1 = bb, acc2 = bb, acc3 = bb;

    const float* wbase = W1 + (size_t)(isb ? 128 : 0)*NH + gcol;

    #pragma unroll
    for (int kc = 0; kc < 128; kc += 64) {
        __syncthreads();
        #pragma unroll
        for (int s = 0; s < 8; s++) {
            int idx = s*128 + tid;         // 1024 float4 = 64 k x 16 quads
            int kk = idx >> 4, q = idx & 15;
            *(float4*)&wseg[kk][q*4] =
                *(const float4*)&wbase[(size_t)(kc + kk)*NH + q*4];
        }
        __syncthreads();

        #pragma unroll 4
        for (int k4 = 0; k4 < 16; k4++) {
            float4 a0 = *(const float4*)&sa[rg*4+0][kc + k4*4];
            float4 a1 = *(const float4*)&sa[rg*4+1][kc + k4*4];
            float4 a2 = *(const float4*)&sa[rg*4+2][kc + k4*4];
            float4 a3 = *(const float4*)&sa[rg*4+3][kc + k4*4];
            #pragma unroll
            for (int u = 0; u < 4; u++) {
                float4 w = *(const float4*)&wseg[k4*4 + u][hq*4];
                float v0 = (u==0)?a0.x:(u==1)?a0.y:(u==2)?a0.z:a0.w;
                float v1 = (u==0)?a1.x:(u==1)?a1.y:(u==2)?a1.z:a1.w;
                float v2 = (u==0)?a2.x:(u==1)?a2.y:(u==2)?a2.z:a2.w;
                float v3 = (u==0)?a3.x:(u==1)?a3.y:(u==2)?a3.z:a3.w;
                acc0.x = fmaf(v0,w.x,acc0.x); acc0.y = fmaf(v0,w.y,acc0.y);
                acc0.z = fmaf(v0,w.z,acc0.z); acc0.w = fmaf(v0,w.w,acc0.w);
                acc1.x = fmaf(v1,w.x,acc1.x); acc1.y = fmaf(v1,w.y,acc1.y);
                acc1.z = fmaf(v1,w.z,acc1.z); acc1.w = fmaf(v1,w.w,acc1.w);
                acc2.x = fmaf(v2,w.x,acc2.x); acc2.y = fmaf(v2,w.y,acc2.y);
                acc2.z = fmaf(v2,w.z,acc2.z); acc2.w = fmaf(v2,w.w,acc2.w);
                acc3.x = fmaf(v3,w.x,acc3.x); acc3.y = fmaf(v3,w.y,acc3.y);
                acc3.z = fmaf(v3,w.z,acc3.z); acc3.w = fmaf(v3,w.w,acc3.w);
            }
        }
    }

    float* dst = isb ? g_hj : g_hi;
    int c = (isb ? hcol0 - 256 : hcol0) + hq*4;
    int r0 = row0 + rg*4;
    *(float4*)&dst[(size_t)(r0+0)*NH + c] = acc0;
    *(float4*)&dst[(size_t)(r0+1)*NH + c] = acc1;
    *(float4*)&dst[(size_t)(r0+2)*NH + c] = acc2;
    *(float4*)&dst[(size_t)(r0+3)*NH + c] = acc3;
}

// ---------------- Kernel B: fused pair-MLP + RBF (R5, best known: 62.0us) ----
#define TI 32
#define TJ 16
#define HCH 128
#define PAD 132

#define PSTEP(A0,A1,C0,C1,W0,W1v) {                                     \
    u64t r00 = relu2(add2((A0), (C0)));                                  \
    u64t r01 = relu2(add2((A0), (C1)));                                  \
    u64t r10 = relu2(add2((A1), (C0)));                                  \
    u64t r11 = relu2(add2((A1), (C1)));                                  \
    acc00a = fma2(r00, (W0), acc00a); acc00b = fma2(r00, (W1v), acc00b); \
    acc01a = fma2(r01, (W0), acc01a); acc01b = fma2(r01, (W1v), acc01b); \
    acc10a = fma2(r10, (W0), acc10a); acc10b = fma2(r10, (W1v), acc10b); \
    acc11a = fma2(r11, (W0), acc11a); acc11b = fma2(r11, (W1v), acc11b); }

__global__ __launch_bounds__(128, 7) void k_fused(
        const float* __restrict__ x,
        const float* __restrict__ W2,
        const float* __restrict__ b2,
        const float* __restrict__ means,
        const float* __restrict__ temps,
        float* __restrict__ out) {
    __shared__ float shi[TI*PAD];          // 16.9 KB, reused for smul/sbias
    __shared__ float shj[TJ*PAD];          // 8.4 KB
    __shared__ float sw0[NH];              // 1 KB
    __shared__ float sw1[NH];              // 1 KB
    __shared__ float sx[TI*TJ];            // 2 KB

    int b  = blockIdx.z;
    int i0 = blockIdx.y * TI;
    int j0 = blockIdx.x * TJ;
    int tid  = threadIdx.x;                // 0..127
    int lane = tid & 31;
    int wid  = tid >> 5;                   // 0..3

    // one-time loads: W2 columns and x tile
    #pragma unroll
    for (int h = tid; h < NH; h += 128) {
        sw0[h] = W2[2*h];
        sw1[h] = W2[2*h + 1];
    }
    {
        int r = tid >> 2;
        int c = tid & 3;
        *(float4*)&sx[r*TJ + c*4] =
            *(const float4*)&x[(size_t)(b*NN + i0 + r)*NN + j0 + c*4];
    }

    const float* hi_base = g_hi + (size_t)(b*NN + i0)*NH;
    const float* hj_base = g_hj + (size_t)(b*NN + j0)*NH;

    int tjj = tid & 7;                     // j rows tjj, tjj+8
    int tii = tid >> 3;                    // i rows tii, tii+16

    u64t acc00a=0ull, acc00b=0ull, acc01a=0ull, acc01b=0ull;
    u64t acc10a=0ull, acc10b=0ull, acc11a=0ull, acc11b=0ull;

    #pragma unroll
    for (int p = 0; p < 2; p++) {
        __syncthreads();
        // stage h-chunk: shi 32x128, shj 16x128 (1536 float4 total)
        #pragma unroll
        for (int s = 0; s < 12; s++) {
            int idx = s*128 + tid;
            if (idx < 1024) {
                int r = idx >> 5, c = idx & 31;
                *(float4*)&shi[r*PAD + c*4] =
                    *(const float4*)&hi_base[(size_t)r*NH + p*HCH + c*4];
            } else {
                int id2 = idx - 1024;
                int r = id2 >> 5, c = id2 & 31;
                *(float4*)&shj[r*PAD + c*4] =
                    *(const float4*)&hj_base[(size_t)r*NH + p*HCH + c*4];
            }
        }
        __syncthreads();

        const float* wp0 = sw0 + p*HCH;
        const float* wp1 = sw1 + p*HCH;
        #pragma unroll 2
        for (int h4 = 0; h4 < HCH/4; h4++) {
            ulonglong2 A0 = *(const ulonglong2*)&shi[(tii   )*PAD + h4*4];
            ulonglong2 A1 = *(const ulonglong2*)&shi[(tii+16)*PAD + h4*4];
            ulonglong2 C0 = *(const ulonglong2*)&shj[(tjj   )*PAD + h4*4];
            ulonglong2 C1 = *(const ulonglong2*)&shj[(tjj+ 8)*PAD + h4*4];
            ulonglong2 W0 = *(const ulonglong2*)&wp0[h4*4];
            ulonglong2 W1v= *(const ulonglong2*)&wp1[h4*4];
            PSTEP(A0.x, A1.x, C0.x, C1.x, W0.x, W1v.x);
            PSTEP(A0.y, A1.y, C0.y, C1.y, W0.y, W1v.y);
        }
    }

    __syncthreads();                       // shi reads done; safe to alias
    float* smul  = shi;                    // 512 floats
    float* sbias = shi + TI*TJ;            // 512 floats (16B-aligned)
    {
        const float s = 0.0625f;           // 1/sqrt(2*128)
        float cb0 = b2[0] * s;
        float cb1 = b2[1] * s;
        smul [(tii   )*TJ + tjj  ] = fmaf(hsum2(acc00a), s, cb0);
        sbias[(tii   )*TJ + tjj  ] = fmaf(hsum2(acc00b), s, cb1);
        smul [(tii   )*TJ + tjj+8] = fmaf(hsum2(acc01a), s, cb0);
        sbias[(tii   )*TJ + tjj+8] = fmaf(hsum2(acc01b), s, cb1);
        smul [(tii+16)*TJ + tjj  ] = fmaf(hsum2(acc10a), s, cb0);
        sbias[(tii+16)*TJ + tjj  ] = fmaf(hsum2(acc10b), s, cb1);
        smul [(tii+16)*TJ + tjj+8] = fmaf(hsum2(acc11a), s, cb0);
        sbias[(tii+16)*TJ + tjj+8] = fmaf(hsum2(acc11b), s, cb1);
    }
    __syncthreads();

    // per-lane RBF constants (phase-local): arg = n*v^2 + p*v + q
    const float L2E = 1.4426950408889634f;
    int k0 = lane * 4;
    float4 mm4 = *(const float4*)&means[k0];
    float4 tt4 = *(const float4*)&temps[k0];
    float nA0 = -fabsf(tt4.x)*L2E, nA1 = -fabsf(tt4.y)*L2E;
    float nA2 = -fabsf(tt4.z)*L2E, nA3 = -fabsf(tt4.w)*L2E;
    float pB0 = -2.f*nA0*mm4.x, pB1 = -2.f*nA1*mm4.y;
    float pB2 = -2.f*nA2*mm4.z, pB3 = -2.f*nA3*mm4.w;
    float qC0 = nA0*mm4.x*mm4.x, qC1 = nA1*mm4.y*mm4.y;
    float qC2 = nA2*mm4.z*mm4.z, qC3 = nA3*mm4.w*mm4.w;

    size_t obase = ((size_t)(b*NN + i0)*NN + j0) * NK + k0;

    #define RBF_ELEM(M,X,BV,OP) {                                        \
        float v = fmaf((M), (X), (BV));                                   \
        float e0 = ex2a(fmaf(fmaf(nA0, v, pB0), v, qC0));                 \
        float e1 = ex2a(fmaf(fmaf(nA1, v, pB1), v, qC1));                 \
        float e2 = ex2a(fmaf(fmaf(nA2, v, pB2), v, qC2));                 \
        float e3 = ex2a(fmaf(fmaf(nA3, v, pB3), v, qC3));                 \
        __stcs((float4*)(OP), make_float4(e0, e1, e2, e3)); }

    #pragma unroll
    for (int ii = 0; ii < 8; ii++) {
        int i_loc = wid*8 + ii;            // 0..31
        const float4* m4p = (const float4*)smul  + i_loc*4;
        const float4* b4p = (const float4*)sbias + i_loc*4;
        const float4* x4p = (const float4*)sx    + i_loc*4;
        float* orow = out + obase + (size_t)i_loc*NN*NK;
        #pragma unroll
        for (int g = 0; g < 4; g++) {
            float4 m4 = m4p[g];
            float4 b4 = b4p[g];
            float4 xv = x4p[g];
            RBF_ELEM(m4.x, xv.x, b4.x, orow + (g*4+0)*NK);
            RBF_ELEM(m4.y, xv.y, b4.y, orow + (g*4+1)*NK);
            RBF_ELEM(m4.z, xv.z, b4.z, orow + (g*4+2)*NK);
            RBF_ELEM(m4.w, xv.w, b4.w, orow + (g*4+3)*NK);
        }
    }
}

// ---------------- launch ------------------------------------------------------
extern "C" void kernel_launch(void* const* d_in, const int* in_sizes, int n_in,
                              void* d_out, int out_size) {
    const float* x     = (const float*)d_in[0];   // (B,N,N)
    const float* ae    = (const float*)d_in[1];   // (B,N,D)
    const float* W1    = (const float*)d_in[2];   // (2D,H)
    const float* b1    = (const float*)d_in[3];   // (H)
    const float* W2    = (const float*)d_in[4];   // (H,2)
    const float* b2    = (const float*)d_in[5];   // (2)
    const float* means = (const float*)d_in[6];   // (K)
    const float* temps = (const float*)d_in[7];   // (K)
    float* out = (float*)d_out;                   // (B,N,N,K)

    dim3 gA(NB*NN/32, 8);                         // (64, 8) = 512 blocks
    k_embed<<<gA, 128>>>(ae, W1, b1);

    dim3 gB(NN/TJ, NN/TI, NB);                    // (16, 8, 8) = 1024 blocks
    k_fused<<<gB, 128>>>(x, W2, b2, means, temps, out);
}